// round 14
// baseline (speedup 1.0000x reference)
#include <cuda_runtime.h>
#include <math.h>

typedef unsigned long long u64;

__device__ __forceinline__ u64 pk2(float lo, float hi) {
    u64 r; asm("mov.b64 %0,{%1,%2};" : "=l"(r) : "f"(lo), "f"(hi)); return r;
}
__device__ __forceinline__ void fma2(u64& d, u64 a, u64 b) {
    asm("fma.rn.f32x2 %0,%1,%2,%0;" : "+l"(d) : "l"(a), "l"(b));
}
__device__ __forceinline__ float2 up2(u64 v) {
    float2 f; asm("mov.b64 {%0,%1},%2;" : "=f"(f.x), "=f"(f.y) : "l"(v)); return f;
}

// ---------------- scratch (device globals; no allocation) ----------------
__device__ float g_h1[512*8*32*32];      // conv1 pooled out [b][oc][32][32]
__device__ float g_h2[512*16*16*16];     // conv2 pooled out [b][oc][16][16]
__device__ float g_feats[512*64*32];     // feats [b][r=64][c=32]
__device__ float g_uhat[512*64*256];     // u_hat [b][r][no=n*8+o]
__device__ float g_v1[512*256];          // v1 [b][n=32][o=8]
__device__ float g_wpad[7968];           // padded conv weights staging

// constant: padded weight groups (12 floats each, 16B aligned) + biases
// layout: w1 groups [24] at 0, w2 groups [128] at 288, w3 groups [512] at 1824
__constant__ float c_wp[7968];
__constant__ float c_b1[8];
__constant__ float c_b2[16];
__constant__ float c_b3[32];

// ---------------- reformat: pad 9-float groups to 12 (staging for constant) ----------------
__global__ __launch_bounds__(256) void reformat_k(const float* __restrict__ w1,
                                                  const float* __restrict__ w2,
                                                  const float* __restrict__ w3) {
    int tid = threadIdx.x;
    for (int i = tid; i < 7968; i += 256) g_wpad[i] = 0.f;
    __syncthreads();
    for (int i = tid; i < 216;  i += 256) { int g = i/9, k = i - g*9; g_wpad[g*12 + k] = w1[i]; }
    for (int i = tid; i < 1152; i += 256) { int g = i/9, k = i - g*9; g_wpad[288 + g*12 + k] = w2[i]; }
    for (int i = tid; i < 4608; i += 256) { int g = i/9, k = i - g*9; g_wpad[1824 + g*12 + k] = w3[i]; }
}

// 9 dup'd weights from constant: 3 uniform LDC.128 + packs (no smem traffic)
__device__ __forceinline__ void ld_w9c(const float* base, u64 wd[9]) {
    const float4* wq = (const float4*)base;
    float4 q0 = wq[0], q1 = wq[1], q2 = wq[2];
    wd[0] = pk2(q0.x,q0.x); wd[1] = pk2(q0.y,q0.y); wd[2] = pk2(q0.z,q0.z);
    wd[3] = pk2(q0.w,q0.w); wd[4] = pk2(q1.x,q1.x); wd[5] = pk2(q1.y,q1.y);
    wd[6] = pk2(q1.z,q1.z); wd[7] = pk2(q1.w,q1.w); wd[8] = pk2(q2.x,q2.x);
}

// ---------------- conv1: [512,3,64,64] -> relu -> pool -> g_h1 (no smem) ----------------
__global__ __launch_bounds__(256) void conv1_k(const float* __restrict__ x) {
    int tid = threadIdx.x;
    int b   = blockIdx.x >> 2;
    int pos = ((blockIdx.x & 3) << 8) + tid;
    int ph = pos >> 5, pw_ = pos & 31;
    int y0 = 2*ph - 1, x0 = 2*pw_ - 1;

    float win[3][4][4];
#pragma unroll
    for (int c = 0; c < 3; c++) {
#pragma unroll
        for (int yy = 0; yy < 4; yy++) {
            int y = y0 + yy;
            bool yok = (y >= 0 && y < 64);
            const float* row = x + ((b*3 + c)*64 + y)*64;
#pragma unroll
            for (int xx = 0; xx < 4; xx++) {
                int xp = x0 + xx;
                win[c][yy][xx] = (yok && xp >= 0 && xp < 64) ? row[xp] : 0.f;
            }
        }
    }

    u64 pwv[3][3][4];
#pragma unroll
    for (int c = 0; c < 3; c++)
#pragma unroll
        for (int ky = 0; ky < 3; ky++)
#pragma unroll
            for (int kx = 0; kx < 4; kx++)
                pwv[c][ky][kx] = pk2(win[c][ky][kx], win[c][ky+1][kx]);

#pragma unroll 1
    for (int oc = 0; oc < 8; oc++) {
        u64 P0 = 0ull, P1 = 0ull;
#pragma unroll
        for (int c = 0; c < 3; c++) {
            u64 wd[9];
            ld_w9c(c_wp + (oc*3 + c)*12, wd);
#pragma unroll
            for (int ky = 0; ky < 3; ky++)
#pragma unroll
                for (int kx = 0; kx < 3; kx++) {
                    u64 ww = wd[ky*3 + kx];
                    fma2(P0, pwv[c][ky][kx],   ww);
                    fma2(P1, pwv[c][ky][kx+1], ww);
                }
        }
        float2 p0 = up2(P0), p1 = up2(P1);
        float m = fmaxf(fmaxf(p0.x, p0.y), fmaxf(p1.x, p1.y)) + c_b1[oc];
        g_h1[((b*8 + oc)*32 + ph)*32 + pw_] = fmaxf(m, 0.f);
    }
}

// ---------------- conv2: (b, oc-half) per block; 8 oc/thread; const weights ----------------
__global__ __launch_bounds__(256) void conv2_k() {
    __shared__ float hs[8192];
    int tid = threadIdx.x;
    int b = blockIdx.x >> 1, half = blockIdx.x & 1;

    {
        const float4* src4 = (const float4*)(g_h1 + b*8192);
        float4* dst4 = (float4*)hs;
#pragma unroll
        for (int k = 0; k < 8; k++) dst4[tid + k*256] = src4[tid + k*256];
    }
    __syncthreads();

    int ph = tid >> 4, pw_ = tid & 15;
    int y0 = 2*ph - 1, x0 = 2*pw_ - 1;

    u64 accP[8][2];
#pragma unroll
    for (int j = 0; j < 8; j++) { accP[j][0] = 0ull; accP[j][1] = 0ull; }

#pragma unroll 1
    for (int ic = 0; ic < 8; ic++) {
        float win[4][4];
#pragma unroll
        for (int yy = 0; yy < 4; yy++) {
            int y = y0 + yy;
            bool yok = (y >= 0 && y < 32);
#pragma unroll
            for (int xx = 0; xx < 4; xx++) {
                int xp = x0 + xx;
                win[yy][xx] = (yok && xp >= 0 && xp < 32) ? hs[ic*1024 + y*32 + xp] : 0.f;
            }
        }
        u64 pwv[3][4];
#pragma unroll
        for (int ky = 0; ky < 3; ky++)
#pragma unroll
            for (int kx = 0; kx < 4; kx++)
                pwv[ky][kx] = pk2(win[ky][kx], win[ky+1][kx]);

#pragma unroll
        for (int j = 0; j < 8; j++) {
            int oc = half*8 + j;
            u64 wd[9];
            ld_w9c(c_wp + 288 + (oc*8 + ic)*12, wd);
#pragma unroll
            for (int ky = 0; ky < 3; ky++)
#pragma unroll
                for (int kx = 0; kx < 3; kx++) {
                    u64 ww = wd[ky*3 + kx];
                    fma2(accP[j][0], pwv[ky][kx],   ww);
                    fma2(accP[j][1], pwv[ky][kx+1], ww);
                }
        }
    }
#pragma unroll
    for (int j = 0; j < 8; j++) {
        int oc = half*8 + j;
        float2 p0 = up2(accP[j][0]), p1 = up2(accP[j][1]);
        float m = fmaxf(fmaxf(p0.x, p0.y), fmaxf(p1.x, p1.y)) + c_b2[oc];
        g_h2[((b*16 + oc)*16 + ph)*16 + pw_] = fmaxf(m, 0.f);
    }
}

// ---------------- conv3: (b, oc-half) per block; 4 oc/thread; const weights ----------------
__global__ __launch_bounds__(256) void conv3_k() {
    __shared__ float hs[2048];
    int tid = threadIdx.x;
    int b = blockIdx.x >> 1, half = blockIdx.x & 1;

    int pos = tid & 63;
    int jg  = tid >> 6;              // 0..3 -> 4 oc each (warp-uniform)
    int ph = pos >> 3, pw_ = pos & 7;
    int y0 = 2*ph - 1, x0 = 2*pw_ - 1;

    u64 accP[4][2];
#pragma unroll
    for (int j = 0; j < 4; j++) { accP[j][0] = 0ull; accP[j][1] = 0ull; }

#pragma unroll 1
    for (int p = 0; p < 2; p++) {
        __syncthreads();
        {
            const float4* src4 = (const float4*)(g_h2 + b*4096 + p*2048);
            float4* dst4 = (float4*)hs;
#pragma unroll
            for (int k = 0; k < 2; k++) dst4[tid + k*256] = src4[tid + k*256];
        }
        __syncthreads();

#pragma unroll 1
        for (int icl = 0; icl < 8; icl++) {
            float win[4][4];
#pragma unroll
            for (int yy = 0; yy < 4; yy++) {
                int y = y0 + yy;
                bool yok = (y >= 0 && y < 16);
#pragma unroll
                for (int xx = 0; xx < 4; xx++) {
                    int xp = x0 + xx;
                    win[yy][xx] = (yok && xp >= 0 && xp < 16) ? hs[icl*256 + y*16 + xp] : 0.f;
                }
            }
            u64 pwv[3][4];
#pragma unroll
            for (int ky = 0; ky < 3; ky++)
#pragma unroll
                for (int kx = 0; kx < 4; kx++)
                    pwv[ky][kx] = pk2(win[ky][kx], win[ky+1][kx]);

#pragma unroll
            for (int j = 0; j < 4; j++) {
                int oc = half*16 + jg*4 + j;
                u64 wd[9];
                ld_w9c(c_wp + 1824 + (oc*16 + p*8 + icl)*12, wd);
#pragma unroll
                for (int ky = 0; ky < 3; ky++)
#pragma unroll
                    for (int kx = 0; kx < 3; kx++) {
                        u64 ww = wd[ky*3 + kx];
                        fma2(accP[j][0], pwv[ky][kx],   ww);
                        fma2(accP[j][1], pwv[ky][kx+1], ww);
                    }
            }
        }
    }
#pragma unroll
    for (int j = 0; j < 4; j++) {
        int oc = half*16 + jg*4 + j;
        float2 p0 = up2(accP[j][0]), p1 = up2(accP[j][1]);
        float m = fmaxf(fmaxf(p0.x, p0.y), fmaxf(p1.x, p1.y)) + c_b3[oc];
        g_feats[(b*64 + pos)*32 + oc] = fmaxf(m, 0.f);
    }
}

// ---------------- u_hat1: 64-b tile, scalar feats, 512 threads, warp->4 rows (round-8 exact) ----------------
__global__ __launch_bounds__(512, 2) void uhat1_k(const float* __restrict__ rw1) {
    __shared__ float2 Wr[4224];     // [c]*132 + [k4]*33 + [l]
    __shared__ float fe[2048];      // [b_local 64][c 32]
    int tid = threadIdx.x;
    int r     = blockIdx.x >> 3;
    int bbase = (blockIdx.x & 7) * 64;

#pragma unroll
    for (int ch = 0; ch < 8; ch++) {
        int i = tid + ch*512;
        int l = i >> 7, j = i & 127;
        float2 v = ((const float2*)(rw1 + (l*64 + r)*256))[j];
        int c = j >> 2, k4 = j & 3;
        Wr[c*132 + k4*33 + l] = v;
    }
#pragma unroll
    for (int k = 0; k < 4; k++) {
        int i = tid + k*512;
        int bb = i >> 5, c = i & 31;
        fe[i] = g_feats[((bbase + bb)*64 + r)*32 + c];
    }
    __syncthreads();

    int wd = tid >> 5, l = tid & 31;
    const u64* WrU = (const u64*)Wr;
    const float* fp = fe + wd*4*32;

    u64 acc[4][4];
#pragma unroll
    for (int j = 0; j < 4; j++)
#pragma unroll
        for (int k4 = 0; k4 < 4; k4++) acc[j][k4] = 0ull;

#pragma unroll 2
    for (int cc = 0; cc < 32; cc++) {
        u64 wv0 = WrU[cc*132 +  0 + l];
        u64 wv1 = WrU[cc*132 + 33 + l];
        u64 wv2 = WrU[cc*132 + 66 + l];
        u64 wv3 = WrU[cc*132 + 99 + l];
#pragma unroll
        for (int j = 0; j < 4; j++) {
            float fv = fp[j*32 + cc];           // broadcast
            u64 f = pk2(fv, fv);
            fma2(acc[j][0], f, wv0);
            fma2(acc[j][1], f, wv1);
            fma2(acc[j][2], f, wv2);
            fma2(acc[j][3], f, wv3);
        }
    }

#pragma unroll
    for (int j = 0; j < 4; j++) {
        float2 p0 = up2(acc[j][0]), p1 = up2(acc[j][1]);
        float2 p2 = up2(acc[j][2]), p3 = up2(acc[j][3]);
        float4* dst = (float4*)(g_uhat + ((bbase + wd*4 + j)*64 + r)*256 + l*8);
        dst[0] = make_float4(p0.x, p0.y, p1.x, p1.y);
        dst[1] = make_float4(p2.x, p2.y, p3.x, p3.y);
    }
}

// ---------------- routing1: block per (b, 16-n half), warp per n; float4 fill ----------------
__global__ __launch_bounds__(512) void route1_k() {
    __shared__ float uh[64*129];
    __shared__ float cc_s[16*64];
    __shared__ float vv_s[16*8];
    int tid = threadIdx.x;
    int w = tid >> 5, lane = tid & 31;
    int b  = blockIdx.x >> 1;
    int ng = blockIdx.x & 1;
    const float4* src4 = (const float4*)(g_uhat + b*16384 + ng*128);

#pragma unroll
    for (int k = 0; k < 4; k++) {
        int i = tid + k*512;
        int r = i >> 5, j4 = i & 31;
        float4 v = src4[r*64 + j4];
        int base = r*129 + j4*4;
        uh[base] = v.x; uh[base+1] = v.y; uh[base+2] = v.z; uh[base+3] = v.w;
    }
    __syncthreads();

    float b0 = 0.f, b1 = 0.f;
    for (int it = 0; it < 3; it++) {
        float c0, c1;
        if (it == 0) {
            c0 = c1 = 1.f/64.f;
        } else {
            float m = fmaxf(b0, b1);
#pragma unroll
            for (int off = 16; off; off >>= 1) m = fmaxf(m, __shfl_xor_sync(0xffffffffu, m, off));
            float e0 = expf(b0 - m), e1 = expf(b1 - m);
            float s = e0 + e1;
#pragma unroll
            for (int off = 16; off; off >>= 1) s += __shfl_xor_sync(0xffffffffu, s, off);
            float inv = 1.f/s;
            c0 = e0*inv; c1 = e1*inv;
        }
        cc_s[w*64 + lane]      = c0;
        cc_s[w*64 + lane + 32] = c1;
        __syncwarp();

        int o = lane & 7, g = lane >> 3;
        float a = 0.f;
#pragma unroll 4
        for (int rr = 0; rr < 16; rr++) {
            int r = g*16 + rr;
            a += cc_s[w*64 + r] * uh[r*129 + w*8 + o];
        }
        a += __shfl_down_sync(0xffffffffu, a, 16);
        a += __shfl_down_sync(0xffffffffu, a, 8);

        if (lane < 8) {
            float n2 = a*a;
            n2 += __shfl_xor_sync(0x000000ffu, n2, 1);
            n2 += __shfl_xor_sync(0x000000ffu, n2, 2);
            n2 += __shfl_xor_sync(0x000000ffu, n2, 4);
            float scale = n2/((1.f + n2)*sqrtf(n2 + 1e-9f));
            vv_s[w*8 + lane] = scale*a;
        }
        __syncwarp();

        if (it < 2) {
            float d0 = 0.f, d1 = 0.f;
#pragma unroll
            for (int o2 = 0; o2 < 8; o2++) {
                float v = vv_s[w*8 + o2];
                d0 += uh[lane*129 + w*8 + o2]*v;
                d1 += uh[(lane + 32)*129 + w*8 + o2]*v;
            }
            b0 += d0; b1 += d1;
            __syncwarp();
        }
    }
    if (lane < 8) g_v1[b*256 + ng*128 + w*8 + lane] = vv_s[w*8 + lane];
}

// ---------------- routing2 + FC: block per 2 b, warp per n (proven) ----------------
__global__ __launch_bounds__(512) void route2_k(const float* __restrict__ rw2,
                                                const float* __restrict__ fcw,
                                                const float* __restrict__ fcb,
                                                float* __restrict__ out) {
    __shared__ float fe_s[512];
    __shared__ float vv2[480];
    int tid = threadIdx.x, w = tid >> 5, lane = tid & 31;
    int b0 = blockIdx.x * 2;
    fe_s[tid] = g_v1[b0*256 + tid];
    __syncthreads();

    if (w < 15) {
        float ua[16], ub[16];
#pragma unroll
        for (int o = 0; o < 16; o++) { ua[o] = 0.f; ub[o] = 0.f; }
        const float4* wp = (const float4*)(rw2 + (w*32 + lane)*128);
#pragma unroll
        for (int c = 0; c < 8; c++) {
            float fa = fe_s[lane*8 + c], fb = fe_s[256 + lane*8 + c];
#pragma unroll
            for (int q = 0; q < 4; q++) {
                float4 wv = wp[c*4 + q];
                ua[q*4+0] += fa*wv.x; ua[q*4+1] += fa*wv.y; ua[q*4+2] += fa*wv.z; ua[q*4+3] += fa*wv.w;
                ub[q*4+0] += fb*wv.x; ub[q*4+1] += fb*wv.y; ub[q*4+2] += fb*wv.z; ub[q*4+3] += fb*wv.w;
            }
        }

        float bij0 = 0.f, bij1 = 0.f;
        for (int it = 0; it < 3; it++) {
            float c0, c1;
            if (it == 0) {
                c0 = c1 = 1.f/32.f;
            } else {
                float m0 = bij0, m1 = bij1;
#pragma unroll
                for (int off = 16; off; off >>= 1) {
                    m0 = fmaxf(m0, __shfl_xor_sync(0xffffffffu, m0, off));
                    m1 = fmaxf(m1, __shfl_xor_sync(0xffffffffu, m1, off));
                }
                float e0 = expf(bij0 - m0), e1 = expf(bij1 - m1);
                float s0 = e0, s1 = e1;
#pragma unroll
                for (int off = 16; off; off >>= 1) {
                    s0 += __shfl_xor_sync(0xffffffffu, s0, off);
                    s1 += __shfl_xor_sync(0xffffffffu, s1, off);
                }
                c0 = e0/s0; c1 = e1/s1;
            }
            float sa[16], sb[16];
#pragma unroll
            for (int o = 0; o < 16; o++) { sa[o] = c0*ua[o]; sb[o] = c1*ub[o]; }
#pragma unroll
            for (int off = 16; off; off >>= 1) {
#pragma unroll
                for (int o = 0; o < 16; o++) {
                    sa[o] += __shfl_xor_sync(0xffffffffu, sa[o], off);
                    sb[o] += __shfl_xor_sync(0xffffffffu, sb[o], off);
                }
            }
            float na = 0.f, nb = 0.f;
#pragma unroll
            for (int o = 0; o < 16; o++) { na += sa[o]*sa[o]; nb += sb[o]*sb[o]; }
            float sca = na/((1.f + na)*sqrtf(na + 1e-9f));
            float scb = nb/((1.f + nb)*sqrtf(nb + 1e-9f));
#pragma unroll
            for (int o = 0; o < 16; o++) { sa[o] *= sca; sb[o] *= scb; }

            if (it < 2) {
                float d0 = 0.f, d1 = 0.f;
#pragma unroll
                for (int o = 0; o < 16; o++) { d0 += ua[o]*sa[o]; d1 += ub[o]*sb[o]; }
                bij0 += d0; bij1 += d1;
            } else if (lane == 0) {
#pragma unroll
                for (int o = 0; o < 16; o++) {
                    vv2[w*16 + o]       = sa[o];
                    vv2[240 + w*16 + o] = sb[o];
                }
            }
        }
    }
    __syncthreads();

    if (w < 15) {
        float a0 = 0.f, a1 = 0.f;
        for (int j = lane; j < 240; j += 32) {
            float wv = fcw[w*240 + j];
            a0 += vv2[j]*wv;
            a1 += vv2[240 + j]*wv;
        }
#pragma unroll
        for (int off = 16; off; off >>= 1) {
            a0 += __shfl_xor_sync(0xffffffffu, a0, off);
            a1 += __shfl_xor_sync(0xffffffffu, a1, off);
        }
        if (lane == 0) {
            float bb = fcb[w];
            out[b0*15 + w]       = a0 + bb;
            out[(b0 + 1)*15 + w] = a1 + bb;
        }
    }
}

// ---------------- launch ----------------
extern "C" void kernel_launch(void* const* d_in, const int* in_sizes, int n_in,
                              void* d_out, int out_size) {
    const float* x   = (const float*)d_in[0];
    const float* w1  = (const float*)d_in[1];
    const float* b1  = (const float*)d_in[2];
    const float* w2  = (const float*)d_in[3];
    const float* b2  = (const float*)d_in[4];
    const float* w3  = (const float*)d_in[5];
    const float* b3  = (const float*)d_in[6];
    const float* rw1 = (const float*)d_in[7];
    const float* rw2 = (const float*)d_in[8];
    const float* fcw = (const float*)d_in[9];
    const float* fcb = (const float*)d_in[10];
    float* out = (float*)d_out;

    // stage padded weights, then D2D-copy into constant memory (graph-capturable)
    reformat_k<<<1, 256>>>(w1, w2, w3);
    void *p_src = 0, *p_wp = 0, *p_b1 = 0, *p_b2 = 0, *p_b3 = 0;
    cudaGetSymbolAddress(&p_src, g_wpad);
    cudaGetSymbolAddress(&p_wp,  c_wp);
    cudaGetSymbolAddress(&p_b1,  c_b1);
    cudaGetSymbolAddress(&p_b2,  c_b2);
    cudaGetSymbolAddress(&p_b3,  c_b3);
    cudaMemcpyAsync(p_wp, p_src, 7968*sizeof(float), cudaMemcpyDeviceToDevice, 0);
    cudaMemcpyAsync(p_b1, (const void*)b1,  8*sizeof(float), cudaMemcpyDeviceToDevice, 0);
    cudaMemcpyAsync(p_b2, (const void*)b2, 16*sizeof(float), cudaMemcpyDeviceToDevice, 0);
    cudaMemcpyAsync(p_b3, (const void*)b3, 32*sizeof(float), cudaMemcpyDeviceToDevice, 0);

    conv1_k<<<2048, 256>>>(x);
    conv2_k<<<1024, 256>>>();
    conv3_k<<<1024, 256>>>();
    uhat1_k<<<512, 512>>>(rw1);
    route1_k<<<1024, 512>>>();
    route2_k<<<256, 512>>>(rw2, fcw, fcb, out);
}

// round 15
// speedup vs baseline: 1.3106x; 1.3106x over previous
#include <cuda_runtime.h>
#include <math.h>

typedef unsigned long long u64;

__device__ __forceinline__ u64 pk2(float lo, float hi) {
    u64 r; asm("mov.b64 %0,{%1,%2};" : "=l"(r) : "f"(lo), "f"(hi)); return r;
}
__device__ __forceinline__ void fma2(u64& d, u64 a, u64 b) {
    asm("fma.rn.f32x2 %0,%1,%2,%0;" : "+l"(d) : "l"(a), "l"(b));
}
__device__ __forceinline__ float2 up2(u64 v) {
    float2 f; asm("mov.b64 {%0,%1},%2;" : "=f"(f.x), "=f"(f.y) : "l"(v)); return f;
}

// ---------------- scratch (device globals; no allocation) ----------------
__device__ float g_h1[512*8*32*32];      // conv1 pooled out [b][oc][32][32]
__device__ float g_h2[512*16*16*16];     // conv2 pooled out [b][oc][16][16]
__device__ float g_feats[512*64*32];     // feats [b][r=64][c=32]
__device__ float g_uhat[512*64*256];     // u_hat [b][r][no=n*8+o]
__device__ float g_v1[512*256];          // v1 [b][n=32][o=8]

// 9 dup'd weights via 4 broadcast LDS.128 + 1 LDS.64 from padded 10-float2 group
__device__ __forceinline__ void ld_w9(const float2* ws, int base, u64 wd[9]) {
    const float4* wq = (const float4*)(ws + base);
    float4 q0 = wq[0], q1 = wq[1], q2 = wq[2], q3 = wq[3];
    float2 t = ws[base + 8];
    wd[0] = pk2(q0.x,q0.y); wd[1] = pk2(q0.z,q0.w);
    wd[2] = pk2(q1.x,q1.y); wd[3] = pk2(q1.z,q1.w);
    wd[4] = pk2(q2.x,q2.y); wd[5] = pk2(q2.z,q2.w);
    wd[6] = pk2(q3.x,q3.y); wd[7] = pk2(q3.z,q3.w);
    wd[8] = pk2(t.x, t.y);
}

// ---------------- conv1: [512,3,64,64] -> relu -> pool -> g_h1 (round-8 proven) ----------------
__global__ __launch_bounds__(256) void conv1_k(const float* __restrict__ x,
                                               const float* __restrict__ w,
                                               const float* __restrict__ bias) {
    __shared__ float2 ws2[216];
    __shared__ float bs[8];
    int tid = threadIdx.x;
    if (tid < 216) { float v = w[tid]; ws2[tid] = make_float2(v, v); }
    if (tid < 8)   bs[tid] = bias[tid];
    __syncthreads();

    int b   = blockIdx.x >> 2;
    int pos = ((blockIdx.x & 3) << 8) + tid;
    int ph = pos >> 5, pw_ = pos & 31;
    int y0 = 2*ph - 1, x0 = 2*pw_ - 1;

    float win[3][4][4];
#pragma unroll
    for (int c = 0; c < 3; c++) {
#pragma unroll
        for (int yy = 0; yy < 4; yy++) {
            int y = y0 + yy;
            bool yok = (y >= 0 && y < 64);
            const float* row = x + ((b*3 + c)*64 + y)*64;
#pragma unroll
            for (int xx = 0; xx < 4; xx++) {
                int xp = x0 + xx;
                win[c][yy][xx] = (yok && xp >= 0 && xp < 64) ? row[xp] : 0.f;
            }
        }
    }

    u64 pwv[3][3][4];
#pragma unroll
    for (int c = 0; c < 3; c++)
#pragma unroll
        for (int ky = 0; ky < 3; ky++)
#pragma unroll
            for (int kx = 0; kx < 4; kx++)
                pwv[c][ky][kx] = pk2(win[c][ky][kx], win[c][ky+1][kx]);

    const u64* wsu = (const u64*)ws2;
#pragma unroll 1
    for (int oc = 0; oc < 8; oc++) {
        u64 P0 = 0ull, P1 = 0ull;
        const u64* wp = wsu + oc*27;
#pragma unroll
        for (int c = 0; c < 3; c++)
#pragma unroll
            for (int ky = 0; ky < 3; ky++)
#pragma unroll
                for (int kx = 0; kx < 3; kx++) {
                    u64 wd = wp[c*9 + ky*3 + kx];
                    fma2(P0, pwv[c][ky][kx],   wd);
                    fma2(P1, pwv[c][ky][kx+1], wd);
                }
        float2 p0 = up2(P0), p1 = up2(P1);
        float m = fmaxf(fmaxf(p0.x, p0.y), fmaxf(p1.x, p1.y)) + bs[oc];
        g_h1[((b*8 + oc)*32 + ph)*32 + pw_] = fmaxf(m, 0.f);
    }
}

// ---------------- conv2: (b, oc-half) per block; 8 oc/thread; float4 fill ----------------
__global__ __launch_bounds__(256) void conv2_k(const float* __restrict__ w,
                                               const float* __restrict__ bias) {
    __shared__ float hs[8192];
    __shared__ float2 ws2[640];     // 64 groups * 10 (pad)
    __shared__ float bs[8];
    int tid = threadIdx.x;
    int b = blockIdx.x >> 1, half = blockIdx.x & 1;

    {
        const float4* src4 = (const float4*)(g_h1 + b*8192);
        float4* dst4 = (float4*)hs;
#pragma unroll
        for (int k = 0; k < 8; k++) dst4[tid + k*256] = src4[tid + k*256];
    }
    for (int i = tid; i < 576; i += 256) {
        int g = i/9, k = i - g*9;
        float v = w[half*576 + i];
        ws2[g*10 + k] = make_float2(v, v);
    }
    if (tid < 8) bs[tid] = bias[half*8 + tid];
    __syncthreads();

    int ph = tid >> 4, pw_ = tid & 15;
    int y0 = 2*ph - 1, x0 = 2*pw_ - 1;

    u64 accP[8][2];
#pragma unroll
    for (int j = 0; j < 8; j++) { accP[j][0] = 0ull; accP[j][1] = 0ull; }

#pragma unroll 1
    for (int ic = 0; ic < 8; ic++) {
        float win[4][4];
#pragma unroll
        for (int yy = 0; yy < 4; yy++) {
            int y = y0 + yy;
            bool yok = (y >= 0 && y < 32);
#pragma unroll
            for (int xx = 0; xx < 4; xx++) {
                int xp = x0 + xx;
                win[yy][xx] = (yok && xp >= 0 && xp < 32) ? hs[ic*1024 + y*32 + xp] : 0.f;
            }
        }
        u64 pwv[3][4];
#pragma unroll
        for (int ky = 0; ky < 3; ky++)
#pragma unroll
            for (int kx = 0; kx < 4; kx++)
                pwv[ky][kx] = pk2(win[ky][kx], win[ky+1][kx]);

#pragma unroll
        for (int j = 0; j < 8; j++) {
            u64 wd[9];
            ld_w9(ws2, (j*8 + ic)*10, wd);
#pragma unroll
            for (int ky = 0; ky < 3; ky++)
#pragma unroll
                for (int kx = 0; kx < 3; kx++) {
                    u64 ww = wd[ky*3 + kx];
                    fma2(accP[j][0], pwv[ky][kx],   ww);
                    fma2(accP[j][1], pwv[ky][kx+1], ww);
                }
        }
    }
#pragma unroll
    for (int j = 0; j < 8; j++) {
        int oc = half*8 + j;
        float2 p0 = up2(accP[j][0]), p1 = up2(accP[j][1]);
        float m = fmaxf(fmaxf(p0.x, p0.y), fmaxf(p1.x, p1.y)) + bs[j];
        g_h2[((b*16 + oc)*16 + ph)*16 + pw_] = fmaxf(m, 0.f);
    }
}

// ---------------- conv3: (b, oc-half) per block; 4 oc/thread; FULL image smem ----------------
__global__ __launch_bounds__(256) void conv3_k(const float* __restrict__ w,
                                               const float* __restrict__ bias) {
    __shared__ float2 ws2[2560];    // 256 groups * 10 (20480 B)
    __shared__ float hs[4096];      // full image 16 KB
    __shared__ float bs[16];
    int tid = threadIdx.x;
    int b = blockIdx.x >> 1, half = blockIdx.x & 1;

    {
        const float4* src4 = (const float4*)(g_h2 + b*4096);
        float4* dst4 = (float4*)hs;
#pragma unroll
        for (int k = 0; k < 4; k++) dst4[tid + k*256] = src4[tid + k*256];
    }
    for (int i = tid; i < 2304; i += 256) {
        int g = i/9, k = i - g*9;
        float v = w[half*2304 + i];
        ws2[g*10 + k] = make_float2(v, v);
    }
    if (tid < 16) bs[tid] = bias[half*16 + tid];
    __syncthreads();

    int pos = tid & 63;
    int jg  = tid >> 6;              // 0..3 -> 4 oc each
    int ph = pos >> 3, pw_ = pos & 7;
    int y0 = 2*ph - 1, x0 = 2*pw_ - 1;

    u64 accP[4][2];
#pragma unroll
    for (int j = 0; j < 4; j++) { accP[j][0] = 0ull; accP[j][1] = 0ull; }

#pragma unroll 1
    for (int ic = 0; ic < 16; ic++) {
        float win[4][4];
#pragma unroll
        for (int yy = 0; yy < 4; yy++) {
            int y = y0 + yy;
            bool yok = (y >= 0 && y < 16);
#pragma unroll
            for (int xx = 0; xx < 4; xx++) {
                int xp = x0 + xx;
                win[yy][xx] = (yok && xp >= 0 && xp < 16) ? hs[ic*256 + y*16 + xp] : 0.f;
            }
        }
        u64 pwv[3][4];
#pragma unroll
        for (int ky = 0; ky < 3; ky++)
#pragma unroll
            for (int kx = 0; kx < 4; kx++)
                pwv[ky][kx] = pk2(win[ky][kx], win[ky+1][kx]);

#pragma unroll
        for (int j = 0; j < 4; j++) {
            u64 wd[9];
            ld_w9(ws2, ((jg*4 + j)*16 + ic)*10, wd);
#pragma unroll
            for (int ky = 0; ky < 3; ky++)
#pragma unroll
                for (int kx = 0; kx < 3; kx++) {
                    u64 ww = wd[ky*3 + kx];
                    fma2(accP[j][0], pwv[ky][kx],   ww);
                    fma2(accP[j][1], pwv[ky][kx+1], ww);
                }
        }
    }
#pragma unroll
    for (int j = 0; j < 4; j++) {
        int oc = half*16 + jg*4 + j;
        float2 p0 = up2(accP[j][0]), p1 = up2(accP[j][1]);
        float m = fmaxf(fmaxf(p0.x, p0.y), fmaxf(p1.x, p1.y)) + bs[jg*4 + j];
        g_feats[(b*64 + pos)*32 + oc] = fmaxf(m, 0.f);
    }
}

// ---------------- u_hat1: 64-b tile, scalar feats, 512 threads, warp->4 rows (round-8 exact) ----------------
__global__ __launch_bounds__(512, 2) void uhat1_k(const float* __restrict__ rw1) {
    __shared__ float2 Wr[4224];     // [c]*132 + [k4]*33 + [l]
    __shared__ float fe[2048];      // [b_local 64][c 32]
    int tid = threadIdx.x;
    int r     = blockIdx.x >> 3;
    int bbase = (blockIdx.x & 7) * 64;

#pragma unroll
    for (int ch = 0; ch < 8; ch++) {
        int i = tid + ch*512;
        int l = i >> 7, j = i & 127;
        float2 v = ((const float2*)(rw1 + (l*64 + r)*256))[j];
        int c = j >> 2, k4 = j & 3;
        Wr[c*132 + k4*33 + l] = v;
    }
#pragma unroll
    for (int k = 0; k < 4; k++) {
        int i = tid + k*512;
        int bb = i >> 5, c = i & 31;
        fe[i] = g_feats[((bbase + bb)*64 + r)*32 + c];
    }
    __syncthreads();

    int wd = tid >> 5, l = tid & 31;
    const u64* WrU = (const u64*)Wr;
    const float* fp = fe + wd*4*32;

    u64 acc[4][4];
#pragma unroll
    for (int j = 0; j < 4; j++)
#pragma unroll
        for (int k4 = 0; k4 < 4; k4++) acc[j][k4] = 0ull;

#pragma unroll 2
    for (int cc = 0; cc < 32; cc++) {
        u64 wv0 = WrU[cc*132 +  0 + l];
        u64 wv1 = WrU[cc*132 + 33 + l];
        u64 wv2 = WrU[cc*132 + 66 + l];
        u64 wv3 = WrU[cc*132 + 99 + l];
#pragma unroll
        for (int j = 0; j < 4; j++) {
            float fv = fp[j*32 + cc];           // broadcast
            u64 f = pk2(fv, fv);
            fma2(acc[j][0], f, wv0);
            fma2(acc[j][1], f, wv1);
            fma2(acc[j][2], f, wv2);
            fma2(acc[j][3], f, wv3);
        }
    }

#pragma unroll
    for (int j = 0; j < 4; j++) {
        float2 p0 = up2(acc[j][0]), p1 = up2(acc[j][1]);
        float2 p2 = up2(acc[j][2]), p3 = up2(acc[j][3]);
        float4* dst = (float4*)(g_uhat + ((bbase + wd*4 + j)*64 + r)*256 + l*8);
        dst[0] = make_float4(p0.x, p0.y, p1.x, p1.y);
        dst[1] = make_float4(p2.x, p2.y, p3.x, p3.y);
    }
}

// ---------------- routing1: block per (b, 16-n half), warp per n; float4 fill ----------------
__global__ __launch_bounds__(512) void route1_k() {
    __shared__ float uh[64*129];
    __shared__ float cc_s[16*64];
    __shared__ float vv_s[16*8];
    int tid = threadIdx.x;
    int w = tid >> 5, lane = tid & 31;
    int b  = blockIdx.x >> 1;
    int ng = blockIdx.x & 1;
    const float4* src4 = (const float4*)(g_uhat + b*16384 + ng*128);

#pragma unroll
    for (int k = 0; k < 4; k++) {
        int i = tid + k*512;
        int r = i >> 5, j4 = i & 31;
        float4 v = src4[r*64 + j4];
        int base = r*129 + j4*4;
        uh[base] = v.x; uh[base+1] = v.y; uh[base+2] = v.z; uh[base+3] = v.w;
    }
    __syncthreads();

    float b0 = 0.f, b1 = 0.f;
    for (int it = 0; it < 3; it++) {
        float c0, c1;
        if (it == 0) {
            c0 = c1 = 1.f/64.f;
        } else {
            float m = fmaxf(b0, b1);
#pragma unroll
            for (int off = 16; off; off >>= 1) m = fmaxf(m, __shfl_xor_sync(0xffffffffu, m, off));
            float e0 = expf(b0 - m), e1 = expf(b1 - m);
            float s = e0 + e1;
#pragma unroll
            for (int off = 16; off; off >>= 1) s += __shfl_xor_sync(0xffffffffu, s, off);
            float inv = 1.f/s;
            c0 = e0*inv; c1 = e1*inv;
        }
        cc_s[w*64 + lane]      = c0;
        cc_s[w*64 + lane + 32] = c1;
        __syncwarp();

        int o = lane & 7, g = lane >> 3;
        float a = 0.f;
#pragma unroll 4
        for (int rr = 0; rr < 16; rr++) {
            int r = g*16 + rr;
            a += cc_s[w*64 + r] * uh[r*129 + w*8 + o];
        }
        a += __shfl_down_sync(0xffffffffu, a, 16);
        a += __shfl_down_sync(0xffffffffu, a, 8);

        if (lane < 8) {
            float n2 = a*a;
            n2 += __shfl_xor_sync(0x000000ffu, n2, 1);
            n2 += __shfl_xor_sync(0x000000ffu, n2, 2);
            n2 += __shfl_xor_sync(0x000000ffu, n2, 4);
            float scale = n2/((1.f + n2)*sqrtf(n2 + 1e-9f));
            vv_s[w*8 + lane] = scale*a;
        }
        __syncwarp();

        if (it < 2) {
            float d0 = 0.f, d1 = 0.f;
#pragma unroll
            for (int o2 = 0; o2 < 8; o2++) {
                float v = vv_s[w*8 + o2];
                d0 += uh[lane*129 + w*8 + o2]*v;
                d1 += uh[(lane + 32)*129 + w*8 + o2]*v;
            }
            b0 += d0; b1 += d1;
            __syncwarp();
        }
    }
    if (lane < 8) g_v1[b*256 + ng*128 + w*8 + lane] = vv_s[w*8 + lane];
}

// ---------------- routing2 + FC: block per 2 b, warp per n (proven) ----------------
__global__ __launch_bounds__(512) void route2_k(const float* __restrict__ rw2,
                                                const float* __restrict__ fcw,
                                                const float* __restrict__ fcb,
                                                float* __restrict__ out) {
    __shared__ float fe_s[512];
    __shared__ float vv2[480];
    int tid = threadIdx.x, w = tid >> 5, lane = tid & 31;
    int b0 = blockIdx.x * 2;
    fe_s[tid] = g_v1[b0*256 + tid];
    __syncthreads();

    if (w < 15) {
        float ua[16], ub[16];
#pragma unroll
        for (int o = 0; o < 16; o++) { ua[o] = 0.f; ub[o] = 0.f; }
        const float4* wp = (const float4*)(rw2 + (w*32 + lane)*128);
#pragma unroll
        for (int c = 0; c < 8; c++) {
            float fa = fe_s[lane*8 + c], fb = fe_s[256 + lane*8 + c];
#pragma unroll
            for (int q = 0; q < 4; q++) {
                float4 wv = wp[c*4 + q];
                ua[q*4+0] += fa*wv.x; ua[q*4+1] += fa*wv.y; ua[q*4+2] += fa*wv.z; ua[q*4+3] += fa*wv.w;
                ub[q*4+0] += fb*wv.x; ub[q*4+1] += fb*wv.y; ub[q*4+2] += fb*wv.z; ub[q*4+3] += fb*wv.w;
            }
        }

        float bij0 = 0.f, bij1 = 0.f;
        for (int it = 0; it < 3; it++) {
            float c0, c1;
            if (it == 0) {
                c0 = c1 = 1.f/32.f;
            } else {
                float m0 = bij0, m1 = bij1;
#pragma unroll
                for (int off = 16; off; off >>= 1) {
                    m0 = fmaxf(m0, __shfl_xor_sync(0xffffffffu, m0, off));
                    m1 = fmaxf(m1, __shfl_xor_sync(0xffffffffu, m1, off));
                }
                float e0 = expf(bij0 - m0), e1 = expf(bij1 - m1);
                float s0 = e0, s1 = e1;
#pragma unroll
                for (int off = 16; off; off >>= 1) {
                    s0 += __shfl_xor_sync(0xffffffffu, s0, off);
                    s1 += __shfl_xor_sync(0xffffffffu, s1, off);
                }
                c0 = e0/s0; c1 = e1/s1;
            }
            float sa[16], sb[16];
#pragma unroll
            for (int o = 0; o < 16; o++) { sa[o] = c0*ua[o]; sb[o] = c1*ub[o]; }
#pragma unroll
            for (int off = 16; off; off >>= 1) {
#pragma unroll
                for (int o = 0; o < 16; o++) {
                    sa[o] += __shfl_xor_sync(0xffffffffu, sa[o], off);
                    sb[o] += __shfl_xor_sync(0xffffffffu, sb[o], off);
                }
            }
            float na = 0.f, nb = 0.f;
#pragma unroll
            for (int o = 0; o < 16; o++) { na += sa[o]*sa[o]; nb += sb[o]*sb[o]; }
            float sca = na/((1.f + na)*sqrtf(na + 1e-9f));
            float scb = nb/((1.f + nb)*sqrtf(nb + 1e-9f));
#pragma unroll
            for (int o = 0; o < 16; o++) { sa[o] *= sca; sb[o] *= scb; }

            if (it < 2) {
                float d0 = 0.f, d1 = 0.f;
#pragma unroll
                for (int o = 0; o < 16; o++) { d0 += ua[o]*sa[o]; d1 += ub[o]*sb[o]; }
                bij0 += d0; bij1 += d1;
            } else if (lane == 0) {
#pragma unroll
                for (int o = 0; o < 16; o++) {
                    vv2[w*16 + o]       = sa[o];
                    vv2[240 + w*16 + o] = sb[o];
                }
            }
        }
    }
    __syncthreads();

    if (w < 15) {
        float a0 = 0.f, a1 = 0.f;
        for (int j = lane; j < 240; j += 32) {
            float wv = fcw[w*240 + j];
            a0 += vv2[j]*wv;
            a1 += vv2[240 + j]*wv;
        }
#pragma unroll
        for (int off = 16; off; off >>= 1) {
            a0 += __shfl_xor_sync(0xffffffffu, a0, off);
            a1 += __shfl_xor_sync(0xffffffffu, a1, off);
        }
        if (lane == 0) {
            float bb = fcb[w];
            out[b0*15 + w]       = a0 + bb;
            out[(b0 + 1)*15 + w] = a1 + bb;
        }
    }
}

// ---------------- launch ----------------
extern "C" void kernel_launch(void* const* d_in, const int* in_sizes, int n_in,
                              void* d_out, int out_size) {
    const float* x   = (const float*)d_in[0];
    const float* w1  = (const float*)d_in[1];
    const float* b1  = (const float*)d_in[2];
    const float* w2  = (const float*)d_in[3];
    const float* b2  = (const float*)d_in[4];
    const float* w3  = (const float*)d_in[5];
    const float* b3  = (const float*)d_in[6];
    const float* rw1 = (const float*)d_in[7];
    const float* rw2 = (const float*)d_in[8];
    const float* fcw = (const float*)d_in[9];
    const float* fcb = (const float*)d_in[10];
    float* out = (float*)d_out;

    conv1_k<<<2048, 256>>>(x, w1, b1);
    conv2_k<<<1024, 256>>>(w2, b2);
    conv3_k<<<1024, 256>>>(w3, b3);
    uhat1_k<<<512, 512>>>(rw1);
    route1_k<<<1024, 512>>>();
    route2_k<<<256, 512>>>(rw2, fcw, fcb, out);
}